// round 1
// baseline (speedup 1.0000x reference)
#include <cuda_runtime.h>
#include <math.h>

#define NN 10000
#define EE 160000
#define ET (EE + NN)
#define KIN 64
#define EIN 16
#define HID 128
#define HEADS 4
#define NEGS 0.2f

// ---------------- scratch (static device globals; no allocation) ----------------
__device__ float g_h[2][NN * HID];        // node features ping-pong
__device__ float g_xlr[NN * 1024];        // per-node [xl(512) | xr(512)] for current layer
__device__ float g_asum[NN * EIN];        // segment-sum of edge_attr by dst
__device__ int   g_deg[NN];
__device__ float g_selfA[NN * 17];        // self-loop 16-vec + bias-flag
__device__ int   g_rowptr[NN + 1];
__device__ int   g_cursor[NN];
__device__ int   g_srcs[ET];
__device__ int   g_eids[ET];
__device__ float g_M[3 * 17 * 512];       // composed [edge_W;edge_b] @ We[l]

// ---------------- preprocessing ----------------
__global__ void k_zero() {
    int i = blockIdx.x * blockDim.x + threadIdx.x;
    if (i < NN * EIN) g_asum[i] = 0.f;
    if (i < NN) { g_deg[i] = 0; g_cursor[i] = 0; }
}

__global__ void k_deg(const float* __restrict__ eattr, const int* __restrict__ eidx) {
    int i = blockIdx.x * blockDim.x + threadIdx.x;
    if (i >= EE * EIN) return;
    int e = i >> 4, k = i & 15;
    int d = eidx[EE + e];
    atomicAdd(&g_asum[d * EIN + k], eattr[i]);
    if (k == 0) atomicAdd(&g_deg[d], 1);
}

__global__ void k_scan() {
    __shared__ int sums[1024];
    int t = threadIdx.x;
    const int CH = 10;                      // 1024*10 >= NN
    int base = t * CH;
    int local[CH];
    int run = 0;
#pragma unroll
    for (int i = 0; i < CH; i++) {
        int gi = base + i;
        int v = (gi < NN) ? (g_deg[gi] + 1) : 0;   // +1 self loop
        local[i] = run;
        run += v;
    }
    sums[t] = run;
    __syncthreads();
    for (int off = 1; off < 1024; off <<= 1) {
        int v = (t >= off) ? sums[t - off] : 0;
        __syncthreads();
        sums[t] += v;
        __syncthreads();
    }
    int offset = (t > 0) ? sums[t - 1] : 0;
#pragma unroll
    for (int i = 0; i < CH; i++) {
        int gi = base + i;
        if (gi < NN) g_rowptr[gi] = offset + local[i];
    }
    if (t == 1023) g_rowptr[NN] = sums[1023];
}

__global__ void k_scatter(const int* __restrict__ eidx) {
    int i = blockIdx.x * blockDim.x + threadIdx.x;
    if (i >= ET) return;
    int s, d;
    if (i < EE) { s = eidx[i]; d = eidx[EE + i]; }
    else        { s = i - EE;  d = s; }
    int pos  = atomicAdd(&g_cursor[d], 1);
    int slot = g_rowptr[d] + pos;
    g_srcs[slot] = s;
    g_eids[slot] = i;
}

__global__ void k_selfA() {
    int i = blockIdx.x * blockDim.x + threadIdx.x;
    if (i >= NN) return;
    int dg = g_deg[i];
    float inv = 1.f / fmaxf((float)dg, 1.f);
#pragma unroll
    for (int k = 0; k < EIN; k++)
        g_selfA[i * 17 + k] = g_asum[i * EIN + k] * inv;
    g_selfA[i * 17 + 16] = (dg > 0) ? 1.f : 0.f;   // edge_b contributes only if deg>0
}

// M[l][k][j] = sum_t EW17[k][t] * We[l][t][j];  EW17 = [edge_W(16x128); edge_b(1x128)]
__global__ void k_compose(const float* __restrict__ edge_W,
                          const float* __restrict__ edge_b,
                          const float* __restrict__ We) {
    int idx = blockIdx.x * blockDim.x + threadIdx.x;
    if (idx >= 3 * 17 * 512) return;
    int l = idx / (17 * 512);
    int r = idx - l * (17 * 512);
    int k = r >> 9;
    int j = r & 511;
    const float* wp = We + l * 128 * 512 + j;
    float acc = 0.f;
#pragma unroll 8
    for (int t = 0; t < 128; t++) {
        float ev = (k < 16) ? edge_W[k * 128 + t] : edge_b[t];
        acc += ev * wp[t * 512];
    }
    g_M[idx] = acc;
}

// node embedding: h0 = x @ node_W + node_b   [10000,64]@[64,128]
__global__ void __launch_bounds__(128) k_emb(const float* __restrict__ x,
                                             const float* __restrict__ Wn,
                                             const float* __restrict__ bn) {
    __shared__ float xs[16][64];
    int nb = blockIdx.x * 16;
    int tid = threadIdx.x;
#pragma unroll
    for (int i = 0; i < 8; i++) {
        int idx = tid + i * 128;
        int r = idx >> 6, c = idx & 63;
        int gr = nb + r;
        xs[r][c] = (gr < NN) ? x[gr * 64 + c] : 0.f;
    }
    __syncthreads();
    int c = tid;                    // 0..127
    float acc[16];
#pragma unroll
    for (int n = 0; n < 16; n++) acc[n] = 0.f;
    for (int k = 0; k < 64; k++) {
        float wv = Wn[k * 128 + c];
#pragma unroll
        for (int n = 0; n < 16; n++) acc[n] += xs[n][k] * wv;
    }
    float bb = bn[c];
#pragma unroll
    for (int n = 0; n < 16; n++) {
        int gr = nb + n;
        if (gr < NN) g_h[0][gr * 128 + c] = acc[n] + bb;
    }
}

// ---------------- per-layer GEMM: g_xlr[:, colOff:colOff+512] = h @ W + bias ----------------
__global__ void __launch_bounds__(256) k_gemm(int hinIdx,
                                              const float* __restrict__ W,
                                              const float* __restrict__ bias,
                                              int colOff) {
    __shared__ float As[64][68];
    __shared__ float Bs[64][64];
    const float* H = g_h[hinIdx];
    int bm = blockIdx.x * 64, bn = blockIdx.y * 64;
    int tid = threadIdx.x;
    int tm = (tid >> 4) << 2, tn = (tid & 15) << 2;
    float acc[4][4];
#pragma unroll
    for (int i = 0; i < 4; i++)
#pragma unroll
        for (int j = 0; j < 4; j++) acc[i][j] = 0.f;

    for (int k0 = 0; k0 < 128; k0 += 64) {
#pragma unroll
        for (int i = 0; i < 4; i++) {
            int li = tid + i * 256;             // 0..1023
            int r = li >> 4;                    // 0..63
            int c4 = (li & 15) << 2;            // 0..60
            int gr = bm + r;
            float4 av = make_float4(0.f, 0.f, 0.f, 0.f);
            if (gr < NN) av = *(const float4*)(H + gr * 128 + k0 + c4);
            As[r][c4 + 0] = av.x; As[r][c4 + 1] = av.y;
            As[r][c4 + 2] = av.z; As[r][c4 + 3] = av.w;
            float4 bv = *(const float4*)(W + (k0 + r) * 512 + bn + c4);
            *(float4*)&Bs[r][c4] = bv;
        }
        __syncthreads();
#pragma unroll
        for (int kk = 0; kk < 64; kk++) {
            float a0 = As[tm + 0][kk], a1 = As[tm + 1][kk];
            float a2 = As[tm + 2][kk], a3 = As[tm + 3][kk];
            float4 b = *(const float4*)&Bs[kk][tn];
            acc[0][0] += a0 * b.x; acc[0][1] += a0 * b.y; acc[0][2] += a0 * b.z; acc[0][3] += a0 * b.w;
            acc[1][0] += a1 * b.x; acc[1][1] += a1 * b.y; acc[1][2] += a1 * b.z; acc[1][3] += a1 * b.w;
            acc[2][0] += a2 * b.x; acc[2][1] += a2 * b.y; acc[2][2] += a2 * b.z; acc[2][3] += a2 * b.w;
            acc[3][0] += a3 * b.x; acc[3][1] += a3 * b.y; acc[3][2] += a3 * b.z; acc[3][3] += a3 * b.w;
        }
        __syncthreads();
    }
    float4 bv = *(const float4*)(bias + bn + tn);
#pragma unroll
    for (int i = 0; i < 4; i++) {
        int gr = bm + tm + i;
        if (gr < NN) {
            float4 o;
            o.x = acc[i][0] + bv.x; o.y = acc[i][1] + bv.y;
            o.z = acc[i][2] + bv.z; o.w = acc[i][3] + bv.w;
            *(float4*)(g_xlr + gr * 1024 + colOff + bn + tn) = o;
        }
    }
}

// ---------------- fused GATv2 aggregation: one block per dst node, warp h = head h ----------------
__global__ void __launch_bounds__(128) k_agg(const float* __restrict__ eattr,
                                             const float* __restrict__ att_l,
                                             const float* __restrict__ bias_l,
                                             int lM, float* out_ext, int outIdx) {
    int v = blockIdx.x;
    int t = threadIdx.x;
    int w = t >> 5, lam = t & 31;
    int jbase = w * HID + lam * 4;          // flattened channel h*128 + c

    const float* Ml = g_M + lM * (17 * 512);
    float4 Mreg[17];
#pragma unroll
    for (int k = 0; k < 17; k++)
        Mreg[k] = *(const float4*)(Ml + k * 512 + jbase);

    float4 attv = *(const float4*)(att_l + jbase);
    float4 xrv  = *(const float4*)(g_xlr + v * 1024 + 512 + jbase);

    float acc0 = 0.f, acc1 = 0.f, acc2 = 0.f, acc3 = 0.f;
    float rmax = -INFINITY, denom = 0.f;

    int beg = g_rowptr[v], end = g_rowptr[v + 1];
    for (int i = beg; i < end; i++) {
        int s   = g_srcs[i];
        int eid = g_eids[i];
        float ea[17];
        if (eid < EE) {
            const float4* p = (const float4*)(eattr + eid * 16);
            float4 a0 = p[0], a1 = p[1], a2 = p[2], a3 = p[3];
            ea[0] = a0.x; ea[1] = a0.y; ea[2]  = a0.z; ea[3]  = a0.w;
            ea[4] = a1.x; ea[5] = a1.y; ea[6]  = a1.z; ea[7]  = a1.w;
            ea[8] = a2.x; ea[9] = a2.y; ea[10] = a2.z; ea[11] = a2.w;
            ea[12] = a3.x; ea[13] = a3.y; ea[14] = a3.z; ea[15] = a3.w;
            ea[16] = 1.f;
        } else {
            const float* p = g_selfA + (eid - EE) * 17;
#pragma unroll
            for (int k = 0; k < 17; k++) ea[k] = p[k];
        }
        float4 xlv = *(const float4*)(g_xlr + s * 1024 + jbase);
        float m0 = xrv.x + xlv.x, m1 = xrv.y + xlv.y;
        float m2 = xrv.z + xlv.z, m3 = xrv.w + xlv.w;
#pragma unroll
        for (int k = 0; k < 17; k++) {
            m0 += ea[k] * Mreg[k].x; m1 += ea[k] * Mreg[k].y;
            m2 += ea[k] * Mreg[k].z; m3 += ea[k] * Mreg[k].w;
        }
        m0 = (m0 > 0.f) ? m0 : NEGS * m0;
        m1 = (m1 > 0.f) ? m1 : NEGS * m1;
        m2 = (m2 > 0.f) ? m2 : NEGS * m2;
        m3 = (m3 > 0.f) ? m3 : NEGS * m3;
        float part = m0 * attv.x + m1 * attv.y + m2 * attv.z + m3 * attv.w;
#pragma unroll
        for (int off = 16; off; off >>= 1)
            part += __shfl_xor_sync(0xffffffffu, part, off);
        float logit = part;
        // online softmax
        float nm = fmaxf(rmax, logit);
        float sc = __expf(rmax - nm);
        float p  = __expf(logit - nm);
        denom = denom * sc + p;
        acc0 = acc0 * sc + p * xlv.x;
        acc1 = acc1 * sc + p * xlv.y;
        acc2 = acc2 * sc + p * xlv.z;
        acc3 = acc3 * sc + p * xlv.w;
        rmax = nm;
    }

    __shared__ float sred[HEADS][HID];
    float inv = 1.f / denom;
    sred[w][lam * 4 + 0] = acc0 * inv;
    sred[w][lam * 4 + 1] = acc1 * inv;
    sred[w][lam * 4 + 2] = acc2 * inv;
    sred[w][lam * 4 + 3] = acc3 * inv;
    __syncthreads();

    int c = t;                               // 0..127
    float o = (sred[0][c] + sred[1][c] + sred[2][c] + sred[3][c]) * 0.25f + bias_l[c];
    o = fmaxf(o, 0.f);                       // relu
    float* out = out_ext ? out_ext : g_h[outIdx];
    out[v * HID + c] = o;
}

// ---------------- launch ----------------
extern "C" void kernel_launch(void* const* d_in, const int* in_sizes, int n_in,
                              void* d_out, int out_size) {
    const float* x       = (const float*)d_in[0];
    const int*   eidx    = (const int*)  d_in[1];
    const float* eattr   = (const float*)d_in[2];
    const float* node_W  = (const float*)d_in[3];
    const float* node_b  = (const float*)d_in[4];
    const float* edge_W  = (const float*)d_in[5];
    const float* edge_b  = (const float*)d_in[6];
    const float* Wl      = (const float*)d_in[7];
    const float* bl      = (const float*)d_in[8];
    const float* Wr      = (const float*)d_in[9];
    const float* br      = (const float*)d_in[10];
    const float* We      = (const float*)d_in[11];
    const float* att     = (const float*)d_in[12];
    const float* bias    = (const float*)d_in[13];
    float* out = (float*)d_out;

    k_zero<<<(NN * EIN + 255) / 256, 256>>>();
    k_deg<<<(EE * EIN + 255) / 256, 256>>>(eattr, eidx);
    k_scan<<<1, 1024>>>();
    k_scatter<<<(ET + 255) / 256, 256>>>(eidx);
    k_selfA<<<(NN + 127) / 128, 128>>>();
    k_compose<<<(3 * 17 * 512 + 255) / 256, 256>>>(edge_W, edge_b, We);
    k_emb<<<NN / 16, 128>>>(x, node_W, node_b);

    dim3 gdim((NN + 63) / 64, 8);
    int hin = 0;
    for (int l = 0; l < 3; l++) {
        k_gemm<<<gdim, 256>>>(hin, Wl + l * 128 * 512, bl + l * 512, 0);
        k_gemm<<<gdim, 256>>>(hin, Wr + l * 128 * 512, br + l * 512, 512);
        if (l == 2)
            k_agg<<<NN, 128>>>(eattr, att + l * HEADS * HID, bias + l * HID, l, out, 0);
        else
            k_agg<<<NN, 128>>>(eattr, att + l * HEADS * HID, bias + l * HID, l, (float*)nullptr, 1 - hin);
        hin = 1 - hin;
    }
}